// round 9
// baseline (speedup 1.0000x reference)
#include <cuda_runtime.h>
#include <cuda_fp16.h>
#include <cstdint>

constexpr int CC = 128, HH = 128, WW = 128, HW = HH * WW;
constexpr int NWIN = 31, NPP = NWIN * NWIN, NPATCH = 8 * NPP;   // 7688
constexpr float SCALE = 0.08838834764831845f;                    // 128^-0.5

// phase-1 chunk buffers (64 ch x 64 tok fp16): Q hi, K hi, K lo = 24 KB
constexpr int QHc = 0, KHc = 8192, KLc = 16384;
// phase-2: V hi/lo (128c x 64s fp16, 32 KB) alias phase-1; TB above
constexpr int VHo = 0, VLo = 16384, TBo = 32768;
constexpr int TB_STRIDE = 68;                                    // f32, conflict-free
constexpr int SMEM_TOTAL = TBo + 64 * TB_STRIDE * 4;             // 50176 -> 4 CTAs/SM

__device__ __half g_zbuf[(size_t)NPATCH * 64 * 128];             // [patch][c][t], fp16
__device__ __half g_zpad[2048];                                  // zero dummy for merge edges

__device__ __forceinline__ uint32_t smem_u32(const void* p) {
    uint32_t a;
    asm("{ .reg .u64 t; cvta.to.shared.u64 t, %1; cvt.u32.u64 %0, t; }" : "=r"(a) : "l"(p));
    return a;
}
__device__ __forceinline__ uint32_t sw128(uint32_t off) { return off ^ ((off >> 3) & 0x70); }
__device__ __forceinline__ void sts64(uint32_t a, uint32_t v0, uint32_t v1) {
    asm volatile("st.shared.v2.b32 [%0], {%1, %2};" :: "r"(a), "r"(v0), "r"(v1) : "memory");
}
__device__ __forceinline__ void ldsm4t(uint32_t r[4], uint32_t a) {
    asm volatile("ldmatrix.sync.aligned.m8n8.x4.trans.shared.b16 {%0,%1,%2,%3}, [%4];"
                 : "=r"(r[0]), "=r"(r[1]), "=r"(r[2]), "=r"(r[3]) : "r"(a));
}
__device__ __forceinline__ void ldsm4(uint32_t r[4], uint32_t a) {
    asm volatile("ldmatrix.sync.aligned.m8n8.x4.shared.b16 {%0,%1,%2,%3}, [%4];"
                 : "=r"(r[0]), "=r"(r[1]), "=r"(r[2]), "=r"(r[3]) : "r"(a));
}
__device__ __forceinline__ void mma16816(float c[4], const uint32_t a[4], const uint32_t b[2]) {
    asm volatile(
        "mma.sync.aligned.m16n8k16.row.col.f32.f16.f16.f32 "
        "{%0,%1,%2,%3}, {%4,%5,%6,%7}, {%8,%9}, {%0,%1,%2,%3};"
        : "+f"(c[0]), "+f"(c[1]), "+f"(c[2]), "+f"(c[3])
        : "r"(a[0]), "r"(a[1]), "r"(a[2]), "r"(a[3]), "r"(b[0]), "r"(b[1]));
}
// fp16 pack (single, for Q and P)
__device__ __forceinline__ uint32_t pack2h(float x, float y) {
    __half2 h = __floats2half2_rn(x, y);
    return *reinterpret_cast<uint32_t*>(&h);
}
// fp16 split: x ~= hi + lo, residual ~2^-23
__device__ __forceinline__ void split2h(float x, float y, uint32_t& hi, uint32_t& lo) {
    __half2 h = __floats2half2_rn(x, y);
    float2 hf = __half22float2(h);
    __half2 l = __floats2half2_rn(x - hf.x, y - hf.y);
    hi = *reinterpret_cast<uint32_t*>(&h);
    lo = *reinterpret_cast<uint32_t*>(&l);
}

__global__ __launch_bounds__(128, 4)
void attn_kernel(const float* __restrict__ q, const float* __restrict__ k,
                 const float* __restrict__ v)
{
    extern __shared__ char smem[];
    const uint32_t sb = smem_u32(smem);
    const int tid = threadIdx.x, wp = tid >> 5, lane = tid & 31;
    const int g = blockIdx.x;
    const int b = g / NPP, rr = g - b * NPP;
    const int h0 = (rr / NWIN) * 4, w0 = (rr % NWIN) * 4;
    const size_t pbase = (size_t)b * CC * HW + (size_t)h0 * WW + w0;

    // fragment geometry
    const int r8 = lane & 7, mi4 = lane >> 3;
    const int dmA = (mi4 & 1) << 3, dkA = (mi4 & 2) << 2;
    const uint32_t aXor = ((uint32_t)(32 * wp + 2 * dmA)) ^ ((uint32_t)r8 << 4);
    const int rowB = ((lane >> 3) & 1) * 8 + r8;
    const int ntSel = lane >> 4;
    const uint32_t rXor = (uint32_t)r8 << 4;

    float s[8][4];
#pragma unroll
    for (int i = 0; i < 8; ++i)
#pragma unroll
        for (int j = 0; j < 4; ++j) s[i][j] = 0.f;

    // ===== phase 1: S = Q K^T, 2-term fp16 (qh*kh + qh*kl), two chunks =====
    for (int ck = 0; ck < 2; ++ck) {
#pragma unroll
        for (int it = 0; it < 8; ++it) {
            int idx = tid + (it << 7);
            int cL = idx >> 4, t0 = (idx & 15) << 2;
            int c = ck * 64 + cL;
            size_t gp = pbase + (size_t)c * HW + (size_t)(t0 >> 3) * WW + (t0 & 7);
            float4 qv = *(const float4*)(q + gp);
            float4 kv = *(const float4*)(k + gp);
            uint32_t qh0 = pack2h(qv.x * SCALE, qv.y * SCALE);
            uint32_t qh1 = pack2h(qv.z * SCALE, qv.w * SCALE);
            uint32_t kh0, kl0, kh1, kl1;
            split2h(kv.x, kv.y, kh0, kl0);
            split2h(kv.z, kv.w, kh1, kl1);
            uint32_t off = sw128((uint32_t)(cL * 128 + t0 * 2));
            sts64(sb + QHc + off, qh0, qh1);
            sts64(sb + KHc + off, kh0, kh1);
            sts64(sb + KLc + off, kl0, kl1);
        }
        __syncthreads();
#pragma unroll
        for (int kt = 0; kt < 4; ++kt) {
            uint32_t ah[4];
            ldsm4t(ah, sb + QHc + (uint32_t)((kt * 16 + dkA + r8) * 128) + aXor);
            uint32_t bRowA = sb + KHc + (uint32_t)((kt * 16 + rowB) * 128);
#pragma unroll
            for (int ntp = 0; ntp < 4; ++ntp) {
                uint32_t bh4[4], bl4[4];
                uint32_t baddr = bRowA + ((((uint32_t)(ntp * 2 + ntSel)) << 4) ^ rXor);
                ldsm4t(bh4, baddr);
                ldsm4t(bl4, baddr + (KLc - KHc));
                mma16816(s[2 * ntp], ah, bh4);
                mma16816(s[2 * ntp], ah, bl4);
                mma16816(s[2 * ntp + 1], ah, bh4 + 2);
                mma16816(s[2 * ntp + 1], ah, bl4 + 2);
            }
        }
        __syncthreads();
    }

    // ---- load V [c][s] hi/lo fp16 (aliases phase-1) ----
#pragma unroll
    for (int it = 0; it < 16; ++it) {
        int idx = tid + (it << 7);
        int c = idx >> 4, t0 = (idx & 15) << 2;
        size_t gp = pbase + (size_t)c * HW + (size_t)(t0 >> 3) * WW + (t0 & 7);
        float4 vv = *(const float4*)(v + gp);
        uint32_t vh0, vl0, vh1, vl1;
        split2h(vv.x, vv.y, vh0, vl0);
        split2h(vv.z, vv.w, vh1, vl1);
        uint32_t off = sw128((uint32_t)(c * 128 + t0 * 2));
        sts64(sb + VHo + off, vh0, vh1);
        sts64(sb + VLo + off, vl0, vl1);
    }

    // ---- softmax in registers (row lives in 4 lanes) ----
    float mx0 = -1e30f, mx1 = -1e30f;
#pragma unroll
    for (int nt = 0; nt < 8; ++nt) {
        mx0 = fmaxf(mx0, fmaxf(s[nt][0], s[nt][1]));
        mx1 = fmaxf(mx1, fmaxf(s[nt][2], s[nt][3]));
    }
    mx0 = fmaxf(mx0, __shfl_xor_sync(~0u, mx0, 1));
    mx0 = fmaxf(mx0, __shfl_xor_sync(~0u, mx0, 2));
    mx1 = fmaxf(mx1, __shfl_xor_sync(~0u, mx1, 1));
    mx1 = fmaxf(mx1, __shfl_xor_sync(~0u, mx1, 2));
    float sm0 = 0.f, sm1 = 0.f;
#pragma unroll
    for (int nt = 0; nt < 8; ++nt) {
        s[nt][0] = __expf(s[nt][0] - mx0);
        s[nt][1] = __expf(s[nt][1] - mx0);
        s[nt][2] = __expf(s[nt][2] - mx1);
        s[nt][3] = __expf(s[nt][3] - mx1);
        sm0 += s[nt][0] + s[nt][1];
        sm1 += s[nt][2] + s[nt][3];
    }
    sm0 += __shfl_xor_sync(~0u, sm0, 1);
    sm0 += __shfl_xor_sync(~0u, sm0, 2);
    sm1 += __shfl_xor_sync(~0u, sm1, 1);
    sm1 += __shfl_xor_sync(~0u, sm1, 2);
    const float inv0 = 1.f / sm0, inv1 = 1.f / sm1;

    // P fragments as single fp16 (quant error RMS-cancels over 64 terms)
    uint32_t pfr[4][4];
#pragma unroll
    for (int kt = 0; kt < 4; ++kt) {
        pfr[kt][0] = pack2h(s[2 * kt][0] * inv0, s[2 * kt][1] * inv0);
        pfr[kt][1] = pack2h(s[2 * kt][2] * inv1, s[2 * kt][3] * inv1);
        pfr[kt][2] = pack2h(s[2 * kt + 1][0] * inv0, s[2 * kt + 1][1] * inv0);
        pfr[kt][3] = pack2h(s[2 * kt + 1][2] * inv1, s[2 * kt + 1][3] * inv1);
    }
    __syncthreads();   // V visible

    // ===== phase 2: Z = P V, 2-term (p*vh + p*vl), two channel halves =====
    float* tb = reinterpret_cast<float*>(smem + TBo);
    __half* zg = g_zbuf + (size_t)g * 8192;
    const int trow = 16 * wp + (lane >> 2);

    for (int hv = 0; hv < 2; ++hv) {
        float z[8][4];
#pragma unroll
        for (int i = 0; i < 8; ++i)
#pragma unroll
            for (int j = 0; j < 4; ++j) z[i][j] = 0.f;

#pragma unroll
        for (int kt = 0; kt < 4; ++kt) {
            uint32_t vcol = ((uint32_t)((kt << 5) + (((lane >> 3) & 1) << 4))) ^ rXor;
#pragma unroll
            for (int ntp = 0; ntp < 4; ++ntp) {
                int row = hv * 64 + ntp * 16 + ntSel * 8 + r8;
                uint32_t addr = sb + VHo + (uint32_t)(row * 128) + vcol;
                uint32_t bh4[4], bl4[4];
                ldsm4(bh4, addr);
                ldsm4(bl4, addr + (VLo - VHo));
                mma16816(z[2 * ntp], pfr[kt], bh4);
                mma16816(z[2 * ntp], pfr[kt], bl4);
                mma16816(z[2 * ntp + 1], pfr[kt], bh4 + 2);
                mma16816(z[2 * ntp + 1], pfr[kt], bl4 + 2);
            }
        }
        // transpose z -> [c_local][t] in TB
#pragma unroll
        for (int nt = 0; nt < 8; ++nt) {
            int c0 = 8 * nt + 2 * (lane & 3);
            tb[c0 * TB_STRIDE + trow]           = z[nt][0];
            tb[(c0 + 1) * TB_STRIDE + trow]     = z[nt][1];
            tb[c0 * TB_STRIDE + trow + 8]       = z[nt][2];
            tb[(c0 + 1) * TB_STRIDE + trow + 8] = z[nt][3];
        }
        __syncthreads();
        // coalesced fp16 store: 4 floats -> 2x half2 (8 bytes)
#pragma unroll
        for (int it = 0; it < 8; ++it) {
            int idx = tid + (it << 7);
            int cL = idx >> 4, f = idx & 15;
            float4 val = *reinterpret_cast<const float4*>(tb + cL * TB_STRIDE + 4 * f);
            uint2 u;
            u.x = pack2h(val.x, val.y);
            u.y = pack2h(val.z, val.w);
            __stcs(reinterpret_cast<uint2*>(zg + (hv * 64 + cL) * 64 + 4 * f), u);
        }
        __syncthreads();
    }
}

// ---- merge: out[b][c][h][w] = sum of <=4 fp16 staged contributors ----
__global__ __launch_bounds__(128)
void merge_kernel(float* __restrict__ out)
{
    const int h = blockIdx.x & 127;
    const int b = (blockIdx.x >> 7) & 7;
    const int cchunk = blockIdx.x >> 10;          // 0..3 -> 32 channels
    const int w = threadIdx.x;
    const int phmin = max(0, (h - 4) >> 2), phmax = min(h >> 2, 30);
    const int pwmin = max(0, (w - 4) >> 2), pwmax = min(w >> 2, 30);

    const __half* base[4];
    int n = 0;
    for (int ph = phmin; ph <= phmax; ++ph)
        for (int pw = pwmin; pw <= pwmax; ++pw)
            base[n++] = g_zbuf
                + ((size_t)(b * NPP + ph * NWIN + pw) * 128 + cchunk * 32) * 64
                + (h - 4 * ph) * 8 + (w - 4 * pw);
    while (n < 4) base[n++] = g_zpad;

    float* op = out + ((size_t)(b * 128 + cchunk * 32) * 128 + h) * 128 + w;
    for (int c0 = 0; c0 < 32; c0 += 8) {
        __half v0[8], v1[8], v2[8], v3[8];
#pragma unroll
        for (int u = 0; u < 8; ++u) {
            v0[u] = __ldcs(base[0] + (size_t)(c0 + u) * 64);
            v1[u] = __ldcs(base[1] + (size_t)(c0 + u) * 64);
            v2[u] = __ldcs(base[2] + (size_t)(c0 + u) * 64);
            v3[u] = __ldcs(base[3] + (size_t)(c0 + u) * 64);
        }
#pragma unroll
        for (int u = 0; u < 8; ++u)
            op[(size_t)(c0 + u) * HW] =
                (__half2float(v0[u]) + __half2float(v1[u]))
              + (__half2float(v2[u]) + __half2float(v3[u]));
    }
}

extern "C" void kernel_launch(void* const* d_in, const int* in_sizes, int n_in,
                              void* d_out, int out_size)
{
    const float* q = (const float*)d_in[0];
    const float* k = (const float*)d_in[1];
    const float* v = (const float*)d_in[2];
    float* out = (float*)d_out;

    cudaFuncSetAttribute(attn_kernel,
                         cudaFuncAttributeMaxDynamicSharedMemorySize, SMEM_TOTAL);
    attn_kernel<<<NPATCH, 128, SMEM_TOTAL>>>(q, k, v);
    merge_kernel<<<8 * 128 * 4, 128>>>(out);
}

// round 10
// speedup vs baseline: 1.2475x; 1.2475x over previous
#include <cuda_runtime.h>
#include <cuda_bf16.h>
#include <cuda_fp16.h>
#include <cstdint>

constexpr int CC = 128, HH = 128, WW = 128, HW = HH * WW;
constexpr int NWIN = 31, NPP = NWIN * NWIN, NPATCH = 8 * NPP;   // 7688
constexpr float SCALE = 0.08838834764831845f;                    // 128^-0.5

// phase-1 chunk buffers (64 channels x 64 tokens bf16, hi/lo, Q/K) = 32 KB
constexpr int QHc = 0, QLc = 8192, KHc = 16384, KLc = 24576;
// phase-2: V tiles (128c x 64s hi/lo) alias phase-1; TB transpose buffer above
constexpr int VHo = 0, VLo = 16384, TBo = 32768;
constexpr int TB_STRIDE = 68;                                    // f32, conflict-free
constexpr int SMEM_TOTAL = TBo + 64 * TB_STRIDE * 4;             // 50176 -> 4 CTAs/SM

__device__ __half g_zbuf[(size_t)NPATCH * 64 * 128];             // [patch][c][t], fp16

__device__ __forceinline__ uint32_t smem_u32(const void* p) {
    uint32_t a;
    asm("{ .reg .u64 t; cvta.to.shared.u64 t, %1; cvt.u32.u64 %0, t; }" : "=r"(a) : "l"(p));
    return a;
}
__device__ __forceinline__ uint32_t sw128(uint32_t off) { return off ^ ((off >> 3) & 0x70); }
__device__ __forceinline__ void sts64(uint32_t a, uint32_t v0, uint32_t v1) {
    asm volatile("st.shared.v2.b32 [%0], {%1, %2};" :: "r"(a), "r"(v0), "r"(v1) : "memory");
}
__device__ __forceinline__ void ldsm4t(uint32_t r[4], uint32_t a) {
    asm volatile("ldmatrix.sync.aligned.m8n8.x4.trans.shared.b16 {%0,%1,%2,%3}, [%4];"
                 : "=r"(r[0]), "=r"(r[1]), "=r"(r[2]), "=r"(r[3]) : "r"(a));
}
__device__ __forceinline__ void ldsm4(uint32_t r[4], uint32_t a) {
    asm volatile("ldmatrix.sync.aligned.m8n8.x4.shared.b16 {%0,%1,%2,%3}, [%4];"
                 : "=r"(r[0]), "=r"(r[1]), "=r"(r[2]), "=r"(r[3]) : "r"(a));
}
__device__ __forceinline__ void mma16816(float c[4], const uint32_t a[4], const uint32_t b[2]) {
    asm volatile(
        "mma.sync.aligned.m16n8k16.row.col.f32.bf16.bf16.f32 "
        "{%0,%1,%2,%3}, {%4,%5,%6,%7}, {%8,%9}, {%0,%1,%2,%3};"
        : "+f"(c[0]), "+f"(c[1]), "+f"(c[2]), "+f"(c[3])
        : "r"(a[0]), "r"(a[1]), "r"(a[2]), "r"(a[3]), "r"(b[0]), "r"(b[1]));
}
__device__ __forceinline__ uint32_t pack2h(float x, float y) {
    __half2 h = __floats2half2_rn(x, y);
    return *reinterpret_cast<uint32_t*>(&h);
}
// rounding bf16 split (R5/R7-proven): x ~= hi + lo, residual ~2^-17
__device__ __forceinline__ void split2(float x, float y, uint32_t& hi, uint32_t& lo) {
    __nv_bfloat162 h = __floats2bfloat162_rn(x, y);
    float2 hf = __bfloat1622float2(h);
    __nv_bfloat162 l = __floats2bfloat162_rn(x - hf.x, y - hf.y);
    hi = *reinterpret_cast<uint32_t*>(&h);
    lo = *reinterpret_cast<uint32_t*>(&l);
}

__global__ __launch_bounds__(128, 4)
void attn_kernel(const float* __restrict__ q, const float* __restrict__ k,
                 const float* __restrict__ v)
{
    extern __shared__ char smem[];
    const uint32_t sb = smem_u32(smem);
    const int tid = threadIdx.x, wp = tid >> 5, lane = tid & 31;
    const int g = blockIdx.x;
    const int b = g / NPP, rr = g - b * NPP;
    const int h0 = (rr / NWIN) * 4, w0 = (rr % NWIN) * 4;
    const size_t pbase = (size_t)b * CC * HW + (size_t)h0 * WW + w0;

    const int r8 = lane & 7, mi4 = lane >> 3;
    const int dmA = (mi4 & 1) << 3, dkA = (mi4 & 2) << 2;
    const uint32_t aXor = ((uint32_t)(32 * wp + 2 * dmA)) ^ ((uint32_t)r8 << 4);
    const int rowB = ((lane >> 3) & 1) * 8 + r8;
    const int ntSel = lane >> 4;
    const uint32_t rXor = (uint32_t)r8 << 4;

    float s[8][4];
#pragma unroll
    for (int i = 0; i < 8; ++i)
#pragma unroll
        for (int j = 0; j < 4; ++j) s[i][j] = 0.f;

    // ================= phase 1: S = Q K^T, two 64-channel chunks =================
    for (int ck = 0; ck < 2; ++ck) {
#pragma unroll
        for (int it = 0; it < 8; ++it) {
            int idx = tid + (it << 7);
            int cL = idx >> 4, t0 = (idx & 15) << 2;
            int c = ck * 64 + cL;
            size_t gp = pbase + (size_t)c * HW + (size_t)(t0 >> 3) * WW + (t0 & 7);
            float4 qv = *(const float4*)(q + gp);
            float4 kv = *(const float4*)(k + gp);
            uint32_t qh0, ql0, qh1, ql1, kh0, kl0, kh1, kl1;
            split2(qv.x * SCALE, qv.y * SCALE, qh0, ql0);
            split2(qv.z * SCALE, qv.w * SCALE, qh1, ql1);
            split2(kv.x, kv.y, kh0, kl0);
            split2(kv.z, kv.w, kh1, kl1);
            uint32_t off = sw128((uint32_t)(cL * 128 + t0 * 2));
            sts64(sb + QHc + off, qh0, qh1);
            sts64(sb + QLc + off, ql0, ql1);
            sts64(sb + KHc + off, kh0, kh1);
            sts64(sb + KLc + off, kl0, kl1);
        }
        __syncthreads();
#pragma unroll
        for (int kt = 0; kt < 4; ++kt) {
            uint32_t ah[4], al[4];
            uint32_t aA = sb + QHc + (uint32_t)((kt * 16 + dkA + r8) * 128) + aXor;
            ldsm4t(ah, aA);
            ldsm4t(al, aA + (QLc - QHc));
            uint32_t bRowA = sb + KHc + (uint32_t)((kt * 16 + rowB) * 128);
#pragma unroll
            for (int ntp = 0; ntp < 4; ++ntp) {
                uint32_t bh4[4], bl4[4];
                uint32_t baddr = bRowA + ((((uint32_t)(ntp * 2 + ntSel)) << 4) ^ rXor);
                ldsm4t(bh4, baddr);
                ldsm4t(bl4, baddr + (KLc - KHc));
                mma16816(s[2 * ntp], ah, bh4);
                mma16816(s[2 * ntp], ah, bl4);
                mma16816(s[2 * ntp], al, bh4);
                mma16816(s[2 * ntp + 1], ah, bh4 + 2);
                mma16816(s[2 * ntp + 1], ah, bl4 + 2);
                mma16816(s[2 * ntp + 1], al, bh4 + 2);
            }
        }
        __syncthreads();
    }

    // ---- load V [c][s] hi/lo (aliases phase-1 buffers) ----
#pragma unroll
    for (int it = 0; it < 16; ++it) {
        int idx = tid + (it << 7);
        int c = idx >> 4, t0 = (idx & 15) << 2;
        size_t gp = pbase + (size_t)c * HW + (size_t)(t0 >> 3) * WW + (t0 & 7);
        float4 vv = *(const float4*)(v + gp);
        uint32_t vh0, vl0, vh1, vl1;
        split2(vv.x, vv.y, vh0, vl0);
        split2(vv.z, vv.w, vh1, vl1);
        uint32_t off = sw128((uint32_t)(c * 128 + t0 * 2));
        sts64(sb + VHo + off, vh0, vh1);
        sts64(sb + VLo + off, vl0, vl1);
    }

    // ---- softmax in registers (row lives in 4 lanes) ----
    float mx0 = -1e30f, mx1 = -1e30f;
#pragma unroll
    for (int nt = 0; nt < 8; ++nt) {
        mx0 = fmaxf(mx0, fmaxf(s[nt][0], s[nt][1]));
        mx1 = fmaxf(mx1, fmaxf(s[nt][2], s[nt][3]));
    }
    mx0 = fmaxf(mx0, __shfl_xor_sync(~0u, mx0, 1));
    mx0 = fmaxf(mx0, __shfl_xor_sync(~0u, mx0, 2));
    mx1 = fmaxf(mx1, __shfl_xor_sync(~0u, mx1, 1));
    mx1 = fmaxf(mx1, __shfl_xor_sync(~0u, mx1, 2));
    float sm0 = 0.f, sm1 = 0.f;
#pragma unroll
    for (int nt = 0; nt < 8; ++nt) {
        s[nt][0] = __expf(s[nt][0] - mx0);
        s[nt][1] = __expf(s[nt][1] - mx0);
        s[nt][2] = __expf(s[nt][2] - mx1);
        s[nt][3] = __expf(s[nt][3] - mx1);
        sm0 += s[nt][0] + s[nt][1];
        sm1 += s[nt][2] + s[nt][3];
    }
    sm0 += __shfl_xor_sync(~0u, sm0, 1);
    sm0 += __shfl_xor_sync(~0u, sm0, 2);
    sm1 += __shfl_xor_sync(~0u, sm1, 1);
    sm1 += __shfl_xor_sync(~0u, sm1, 2);
    const float inv0 = 1.f / sm0, inv1 = 1.f / sm1;
    __syncthreads();   // V visible

    // ================= phase 2: Z = P V, two 64-channel halves =================
    float* tb = reinterpret_cast<float*>(smem + TBo);
    __half* zg = g_zbuf + (size_t)g * 8192;
    const int trow = 16 * wp + (lane >> 2);

    for (int hv = 0; hv < 2; ++hv) {
        float z[8][4];
#pragma unroll
        for (int i = 0; i < 8; ++i)
#pragma unroll
            for (int j = 0; j < 4; ++j) z[i][j] = 0.f;

#pragma unroll
        for (int kt = 0; kt < 4; ++kt) {
            uint32_t ph[4], pl[4];
            split2(s[2 * kt][0] * inv0, s[2 * kt][1] * inv0, ph[0], pl[0]);
            split2(s[2 * kt][2] * inv1, s[2 * kt][3] * inv1, ph[1], pl[1]);
            split2(s[2 * kt + 1][0] * inv0, s[2 * kt + 1][1] * inv0, ph[2], pl[2]);
            split2(s[2 * kt + 1][2] * inv1, s[2 * kt + 1][3] * inv1, ph[3], pl[3]);
            uint32_t vcol = ((uint32_t)((kt << 5) + (((lane >> 3) & 1) << 4))) ^ rXor;
#pragma unroll
            for (int ntp = 0; ntp < 4; ++ntp) {
                int row = hv * 64 + ntp * 16 + ntSel * 8 + r8;
                uint32_t addr = sb + VHo + (uint32_t)(row * 128) + vcol;
                uint32_t bh4[4], bl4[4];
                ldsm4(bh4, addr);
                ldsm4(bl4, addr + (VLo - VHo));
                mma16816(z[2 * ntp], ph, bh4);
                mma16816(z[2 * ntp], ph, bl4);
                mma16816(z[2 * ntp], pl, bh4);
                mma16816(z[2 * ntp + 1], ph, bh4 + 2);
                mma16816(z[2 * ntp + 1], ph, bl4 + 2);
                mma16816(z[2 * ntp + 1], pl, bh4 + 2);
            }
        }
#pragma unroll
        for (int nt = 0; nt < 8; ++nt) {
            int c0 = 8 * nt + 2 * (lane & 3);
            tb[c0 * TB_STRIDE + trow]           = z[nt][0];
            tb[(c0 + 1) * TB_STRIDE + trow]     = z[nt][1];
            tb[c0 * TB_STRIDE + trow + 8]       = z[nt][2];
            tb[(c0 + 1) * TB_STRIDE + trow + 8] = z[nt][3];
        }
        __syncthreads();
#pragma unroll
        for (int it = 0; it < 8; ++it) {
            int idx = tid + (it << 7);
            int cL = idx >> 4, f = idx & 15;
            float4 val = *reinterpret_cast<const float4*>(tb + cL * TB_STRIDE + 4 * f);
            uint2 u;
            u.x = pack2h(val.x, val.y);
            u.y = pack2h(val.z, val.w);
            __stcs(reinterpret_cast<uint2*>(zg + (hv * 64 + cL) * 64 + 4 * f), u);
        }
        __syncthreads();
    }
}

// ---- merge v2: row-owner CTA, vectorized 16B patch-segment loads, smem accum ----
__global__ __launch_bounds__(128)
void merge_kernel(float* __restrict__ out)
{
    __shared__ float acc[128 * 33];               // [w][c], pad 33 -> conflict-free
    const int h = blockIdx.x & 127;
    const int b = (blockIdx.x >> 7) & 7;
    const int cch = blockIdx.x >> 10;             // 0..3 -> 32 channels
    const int tid = threadIdx.x;

    for (int i = tid; i < 128 * 33; i += 128) acc[i] = 0.f;
    __syncthreads();

    const int phmin = max(0, (h - 4) >> 2), phmax = min(h >> 2, 30);
    const int c = tid & 31;                       // lane = channel
    const int jbase = tid >> 5;                   // 0..3

    for (int ph = phmin; ph <= phmax; ++ph) {
        const int dh = h - 4 * ph;
        const __half* pz = g_zbuf
            + ((size_t)(b * NPP + ph * NWIN) * 128 + cch * 32 + c) * 64 + dh * 8;
        for (int parity = 0; parity < 2; ++parity) {
            // pw = parity + 2j, j in 0..15 (pw<=30); same-parity segments are w-disjoint
#pragma unroll
            for (int jj = 0; jj < 4; ++jj) {
                int j = jbase * 4 + jj;
                int pw = parity + 2 * j;
                if (pw <= 30) {
                    uint4 u = *reinterpret_cast<const uint4*>(pz + (size_t)pw * 8192);
                    const __half2* hp = reinterpret_cast<const __half2*>(&u);
                    float* a = acc + (4 * pw) * 33 + c;
                    float2 f0 = __half22float2(hp[0]), f1 = __half22float2(hp[1]);
                    float2 f2 = __half22float2(hp[2]), f3 = __half22float2(hp[3]);
                    a[0 * 33] += f0.x; a[1 * 33] += f0.y;
                    a[2 * 33] += f1.x; a[3 * 33] += f1.y;
                    a[4 * 33] += f2.x; a[5 * 33] += f2.y;
                    a[6 * 33] += f3.x; a[7 * 33] += f3.y;
                }
            }
            __syncthreads();
        }
    }

    // coalesced store: 32 rows of 512B; smem reads stride-33 (conflict-free)
    float* op = out + ((size_t)(b * 128 + cch * 32) * 128 + h) * 128;
#pragma unroll 4
    for (int ci = 0; ci < 32; ++ci)
        op[(size_t)ci * HW + tid] = acc[tid * 33 + ci];
}

extern "C" void kernel_launch(void* const* d_in, const int* in_sizes, int n_in,
                              void* d_out, int out_size)
{
    const float* q = (const float*)d_in[0];
    const float* k = (const float*)d_in[1];
    const float* v = (const float*)d_in[2];
    float* out = (float*)d_out;

    cudaFuncSetAttribute(attn_kernel,
                         cudaFuncAttributeMaxDynamicSharedMemorySize, SMEM_TOTAL);
    attn_kernel<<<NPATCH, 128, SMEM_TOTAL>>>(q, k, v);
    merge_kernel<<<8 * 128 * 4, 128>>>(out);
}

// round 12
// speedup vs baseline: 1.3790x; 1.1054x over previous
#include <cuda_runtime.h>
#include <cuda_bf16.h>
#include <cuda_fp16.h>
#include <cstdint>

constexpr int CC = 128, HH = 128, WW = 128, HW = HH * WW;
constexpr int NWIN = 31, NPP = NWIN * NWIN, NPATCH = 8 * NPP;   // 7688
constexpr float SCALE = 0.08838834764831845f;                    // 128^-0.5

// phase-1 chunk buffers (64 channels x 64 tokens bf16, hi/lo, Q/K) = 32 KB
constexpr int QHc = 0, QLc = 8192, KHc = 16384, KLc = 24576;
// phase-2: V tiles (128c x 64s hi/lo) alias phase-1; TBu (packed u32 [64][34]) above
constexpr int VHo = 0, VLo = 16384, TBo = 32768;
constexpr int TBU_S = 34;                                        // u32 stride (EVEN: 8B-aligned uint2)
constexpr int SMEM_TOTAL = TBo + 64 * TBU_S * 4;                 // 41472 -> 4 CTAs/SM

__device__ __half g_zbuf[(size_t)NPATCH * 64 * 128];             // [patch][t][c], fp16

__device__ __forceinline__ uint32_t smem_u32(const void* p) {
    uint32_t a;
    asm("{ .reg .u64 t; cvta.to.shared.u64 t, %1; cvt.u32.u64 %0, t; }" : "=r"(a) : "l"(p));
    return a;
}
__device__ __forceinline__ uint32_t sw128(uint32_t off) { return off ^ ((off >> 3) & 0x70); }
__device__ __forceinline__ void sts64(uint32_t a, uint32_t v0, uint32_t v1) {
    asm volatile("st.shared.v2.b32 [%0], {%1, %2};" :: "r"(a), "r"(v0), "r"(v1) : "memory");
}
__device__ __forceinline__ void ldsm4t(uint32_t r[4], uint32_t a) {
    asm volatile("ldmatrix.sync.aligned.m8n8.x4.trans.shared.b16 {%0,%1,%2,%3}, [%4];"
                 : "=r"(r[0]), "=r"(r[1]), "=r"(r[2]), "=r"(r[3]) : "r"(a));
}
__device__ __forceinline__ void ldsm4(uint32_t r[4], uint32_t a) {
    asm volatile("ldmatrix.sync.aligned.m8n8.x4.shared.b16 {%0,%1,%2,%3}, [%4];"
                 : "=r"(r[0]), "=r"(r[1]), "=r"(r[2]), "=r"(r[3]) : "r"(a));
}
__device__ __forceinline__ void mma16816(float c[4], const uint32_t a[4], const uint32_t b[2]) {
    asm volatile(
        "mma.sync.aligned.m16n8k16.row.col.f32.bf16.bf16.f32 "
        "{%0,%1,%2,%3}, {%4,%5,%6,%7}, {%8,%9}, {%0,%1,%2,%3};"
        : "+f"(c[0]), "+f"(c[1]), "+f"(c[2]), "+f"(c[3])
        : "r"(a[0]), "r"(a[1]), "r"(a[2]), "r"(a[3]), "r"(b[0]), "r"(b[1]));
}
__device__ __forceinline__ uint32_t pack2h(float x, float y) {
    __half2 h = __floats2half2_rn(x, y);
    return *reinterpret_cast<uint32_t*>(&h);
}
// rounding bf16 split (proven): x ~= hi + lo, residual ~2^-17
__device__ __forceinline__ void split2(float x, float y, uint32_t& hi, uint32_t& lo) {
    __nv_bfloat162 h = __floats2bfloat162_rn(x, y);
    float2 hf = __bfloat1622float2(h);
    __nv_bfloat162 l = __floats2bfloat162_rn(x - hf.x, y - hf.y);
    hi = *reinterpret_cast<uint32_t*>(&h);
    lo = *reinterpret_cast<uint32_t*>(&l);
}

__global__ __launch_bounds__(128, 4)
void attn_kernel(const float* __restrict__ q, const float* __restrict__ k,
                 const float* __restrict__ v)
{
    extern __shared__ char smem[];
    const uint32_t sb = smem_u32(smem);
    const int tid = threadIdx.x, wp = tid >> 5, lane = tid & 31;
    const int g = blockIdx.x;
    const int b = g / NPP, rr = g - b * NPP;
    const int h0 = (rr / NWIN) * 4, w0 = (rr % NWIN) * 4;
    const size_t pbase = (size_t)b * CC * HW + (size_t)h0 * WW + w0;

    const int r8 = lane & 7, mi4 = lane >> 3;
    const int dmA = (mi4 & 1) << 3, dkA = (mi4 & 2) << 2;
    const uint32_t aXor = ((uint32_t)(32 * wp + 2 * dmA)) ^ ((uint32_t)r8 << 4);
    const int rowB = ((lane >> 3) & 1) * 8 + r8;
    const int ntSel = lane >> 4;
    const uint32_t rXor = (uint32_t)r8 << 4;

    float s[8][4];
#pragma unroll
    for (int i = 0; i < 8; ++i)
#pragma unroll
        for (int j = 0; j < 4; ++j) s[i][j] = 0.f;

    // ================= phase 1: S = Q K^T, two 64-channel chunks =================
    for (int ck = 0; ck < 2; ++ck) {
#pragma unroll
        for (int it = 0; it < 8; ++it) {
            int idx = tid + (it << 7);
            int cL = idx >> 4, t0 = (idx & 15) << 2;
            int c = ck * 64 + cL;
            size_t gp = pbase + (size_t)c * HW + (size_t)(t0 >> 3) * WW + (t0 & 7);
            float4 qv = *(const float4*)(q + gp);
            float4 kv = *(const float4*)(k + gp);
            uint32_t qh0, ql0, qh1, ql1, kh0, kl0, kh1, kl1;
            split2(qv.x * SCALE, qv.y * SCALE, qh0, ql0);
            split2(qv.z * SCALE, qv.w * SCALE, qh1, ql1);
            split2(kv.x, kv.y, kh0, kl0);
            split2(kv.z, kv.w, kh1, kl1);
            uint32_t off = sw128((uint32_t)(cL * 128 + t0 * 2));
            sts64(sb + QHc + off, qh0, qh1);
            sts64(sb + QLc + off, ql0, ql1);
            sts64(sb + KHc + off, kh0, kh1);
            sts64(sb + KLc + off, kl0, kl1);
        }
        __syncthreads();
#pragma unroll
        for (int kt = 0; kt < 4; ++kt) {
            uint32_t ah[4], al[4];
            uint32_t aA = sb + QHc + (uint32_t)((kt * 16 + dkA + r8) * 128) + aXor;
            ldsm4t(ah, aA);
            ldsm4t(al, aA + (QLc - QHc));
            uint32_t bRowA = sb + KHc + (uint32_t)((kt * 16 + rowB) * 128);
#pragma unroll
            for (int ntp = 0; ntp < 4; ++ntp) {
                uint32_t bh4[4], bl4[4];
                uint32_t baddr = bRowA + ((((uint32_t)(ntp * 2 + ntSel)) << 4) ^ rXor);
                ldsm4t(bh4, baddr);
                ldsm4t(bl4, baddr + (KLc - KHc));
                mma16816(s[2 * ntp], ah, bh4);
                mma16816(s[2 * ntp], ah, bl4);
                mma16816(s[2 * ntp], al, bh4);
                mma16816(s[2 * ntp + 1], ah, bh4 + 2);
                mma16816(s[2 * ntp + 1], ah, bl4 + 2);
                mma16816(s[2 * ntp + 1], al, bh4 + 2);
            }
        }
        __syncthreads();
    }

    // ---- load V [c][s] hi/lo (aliases phase-1 buffers) ----
#pragma unroll
    for (int it = 0; it < 16; ++it) {
        int idx = tid + (it << 7);
        int c = idx >> 4, t0 = (idx & 15) << 2;
        size_t gp = pbase + (size_t)c * HW + (size_t)(t0 >> 3) * WW + (t0 & 7);
        float4 vv = *(const float4*)(v + gp);
        uint32_t vh0, vl0, vh1, vl1;
        split2(vv.x, vv.y, vh0, vl0);
        split2(vv.z, vv.w, vh1, vl1);
        uint32_t off = sw128((uint32_t)(c * 128 + t0 * 2));
        sts64(sb + VHo + off, vh0, vh1);
        sts64(sb + VLo + off, vl0, vl1);
    }

    // ---- softmax in registers (row lives in 4 lanes) ----
    float mx0 = -1e30f, mx1 = -1e30f;
#pragma unroll
    for (int nt = 0; nt < 8; ++nt) {
        mx0 = fmaxf(mx0, fmaxf(s[nt][0], s[nt][1]));
        mx1 = fmaxf(mx1, fmaxf(s[nt][2], s[nt][3]));
    }
    mx0 = fmaxf(mx0, __shfl_xor_sync(~0u, mx0, 1));
    mx0 = fmaxf(mx0, __shfl_xor_sync(~0u, mx0, 2));
    mx1 = fmaxf(mx1, __shfl_xor_sync(~0u, mx1, 1));
    mx1 = fmaxf(mx1, __shfl_xor_sync(~0u, mx1, 2));
    float sm0 = 0.f, sm1 = 0.f;
#pragma unroll
    for (int nt = 0; nt < 8; ++nt) {
        s[nt][0] = __expf(s[nt][0] - mx0);
        s[nt][1] = __expf(s[nt][1] - mx0);
        s[nt][2] = __expf(s[nt][2] - mx1);
        s[nt][3] = __expf(s[nt][3] - mx1);
        sm0 += s[nt][0] + s[nt][1];
        sm1 += s[nt][2] + s[nt][3];
    }
    sm0 += __shfl_xor_sync(~0u, sm0, 1);
    sm0 += __shfl_xor_sync(~0u, sm0, 2);
    sm1 += __shfl_xor_sync(~0u, sm1, 1);
    sm1 += __shfl_xor_sync(~0u, sm1, 2);
    const float inv0 = 1.f / sm0, inv1 = 1.f / sm1;
    __syncthreads();   // V visible

    // ================= phase 2: Z = P V, two 64-channel halves =================
    uint32_t* tbu = reinterpret_cast<uint32_t*>(smem + TBo);   // packed half2 [t][cq]
    __half* zg = g_zbuf + (size_t)g * 8192;
    const int trow = 16 * wp + (lane >> 2);

    for (int hv = 0; hv < 2; ++hv) {
        float z[8][4];
#pragma unroll
        for (int i = 0; i < 8; ++i)
#pragma unroll
            for (int j = 0; j < 4; ++j) z[i][j] = 0.f;

#pragma unroll
        for (int kt = 0; kt < 4; ++kt) {
            uint32_t ph[4], pl[4];
            split2(s[2 * kt][0] * inv0, s[2 * kt][1] * inv0, ph[0], pl[0]);
            split2(s[2 * kt][2] * inv1, s[2 * kt][3] * inv1, ph[1], pl[1]);
            split2(s[2 * kt + 1][0] * inv0, s[2 * kt + 1][1] * inv0, ph[2], pl[2]);
            split2(s[2 * kt + 1][2] * inv1, s[2 * kt + 1][3] * inv1, ph[3], pl[3]);
            uint32_t vcol = ((uint32_t)((kt << 5) + (((lane >> 3) & 1) << 4))) ^ rXor;
#pragma unroll
            for (int ntp = 0; ntp < 4; ++ntp) {
                int row = hv * 64 + ntp * 16 + ntSel * 8 + r8;
                uint32_t addr = sb + VHo + (uint32_t)(row * 128) + vcol;
                uint32_t bh4[4], bl4[4];
                ldsm4(bh4, addr);
                ldsm4(bl4, addr + (VLo - VHo));
                mma16816(z[2 * ntp], ph, bh4);
                mma16816(z[2 * ntp], ph, bl4);
                mma16816(z[2 * ntp], pl, bh4);
                mma16816(z[2 * ntp + 1], ph, bh4 + 2);
                mma16816(z[2 * ntp + 1], ph, bl4 + 2);
                mma16816(z[2 * ntp + 1], pl, bh4 + 2);
            }
        }
        // pack + write TBu [t][cq]  (c pair -> one u32)
#pragma unroll
        for (int nt = 0; nt < 8; ++nt) {
            int cq = 4 * nt + (lane & 3);
            tbu[trow * TBU_S + cq]       = pack2h(z[nt][0], z[nt][1]);
            tbu[(trow + 8) * TBU_S + cq] = pack2h(z[nt][2], z[nt][3]);
        }
        __syncthreads();
        // store zbuf [t][c]: fully coalesced uint2 (stride 34 -> 8B-aligned)
#pragma unroll
        for (int it = 0; it < 8; ++it) {
            int idx = tid + (it << 7);
            int t = idx >> 4, cqp = idx & 15;
            uint2 u = *reinterpret_cast<const uint2*>(tbu + t * TBU_S + 2 * cqp);
            __stcs(reinterpret_cast<uint2*>(zg + t * 128 + hv * 64 + 4 * cqp), u);
        }
        __syncthreads();
    }
}

// ---- merge v3: zbuf [patch][t][c] -> fully coalesced 64B gathers ----
__global__ __launch_bounds__(256)
void merge_kernel(float* __restrict__ out)
{
    __shared__ float acc[128 * 33];               // [w][c], pad 33
    const int h = blockIdx.x & 127;
    const int b = (blockIdx.x >> 7) & 7;
    const int cch = blockIdx.x >> 10;             // 0..3 -> 32 channels
    const int tid = threadIdx.x, wp = tid >> 5, lane = tid & 31;
    const int phmin = max(0, (h - 4) >> 2), phmax = min(h >> 2, 30);

#pragma unroll 4
    for (int wi = 0; wi < 16; ++wi) {
        int w = wp * 16 + wi;                     // warp owns w exclusively
        int pwmin = max(0, (w - 4) >> 2), pwmax = min(w >> 2, 30);
        float a = 0.f;
        for (int ph = phmin; ph <= phmax; ++ph) {
            int dh = h - 4 * ph;
            for (int pw = pwmin; pw <= pwmax; ++pw) {
                int t = dh * 8 + (w - 4 * pw);
                const __half* p = g_zbuf
                    + ((size_t)(b * NPP + ph * NWIN + pw) * 64 + t) * 128
                    + cch * 32 + lane;            // lane = c: 64B contiguous
                a += __half2float(__ldcs(p));
            }
        }
        acc[w * 33 + lane] = a;
    }
    __syncthreads();

    // coalesced store: lane ~ w, 16 channels per thread-half
    const int w = tid & 127, cb = (tid >> 7) * 16;
    float* op = out + ((size_t)(b * 128 + cch * 32 + cb) * 128 + h) * 128 + w;
#pragma unroll
    for (int ci = 0; ci < 16; ++ci)
        op[(size_t)ci * HW] = acc[w * 33 + cb + ci];
}

extern "C" void kernel_launch(void* const* d_in, const int* in_sizes, int n_in,
                              void* d_out, int out_size)
{
    const float* q = (const float*)d_in[0];
    const float* k = (const float*)d_in[1];
    const float* v = (const float*)d_in[2];
    float* out = (float*)d_out;

    cudaFuncSetAttribute(attn_kernel,
                         cudaFuncAttributeMaxDynamicSharedMemorySize, SMEM_TOTAL);
    attn_kernel<<<NPATCH, 128, SMEM_TOTAL>>>(q, k, v);
    merge_kernel<<<8 * 128 * 4, 256>>>(out);
}

// round 13
// speedup vs baseline: 1.5543x; 1.1271x over previous
#include <cuda_runtime.h>
#include <cuda_bf16.h>
#include <cuda_fp16.h>
#include <cstdint>

constexpr int CC = 128, HH = 128, WW = 128, HW = HH * WW;
constexpr int NWIN = 31, NPP = NWIN * NWIN, NPATCH = 8 * NPP;   // 7688
constexpr float SCALE = 0.08838834764831845f;                    // 128^-0.5

// phase-1 chunk buffers (64 channels x 64 tokens bf16, hi/lo, Q/K) = 32 KB
constexpr int QHc = 0, QLc = 8192, KHc = 16384, KLc = 24576;
// phase-2: V tiles (128c x 64s hi/lo) alias phase-1; TBu (packed u32 [64][34]) above
constexpr int VHo = 0, VLo = 16384, TBo = 32768;
constexpr int TBU_S = 34;                                        // u32 stride (EVEN: 8B-aligned uint2)
constexpr int SMEM_TOTAL = TBo + 64 * TBU_S * 4;                 // 41472 -> 5 CTAs/SM

__device__ __half g_zbuf[(size_t)NPATCH * 64 * 128];             // [patch][t][c], fp16

__device__ __forceinline__ uint32_t smem_u32(const void* p) {
    uint32_t a;
    asm("{ .reg .u64 t; cvta.to.shared.u64 t, %1; cvt.u32.u64 %0, t; }" : "=r"(a) : "l"(p));
    return a;
}
__device__ __forceinline__ uint32_t sw128(uint32_t off) { return off ^ ((off >> 3) & 0x70); }
__device__ __forceinline__ void sts64(uint32_t a, uint32_t v0, uint32_t v1) {
    asm volatile("st.shared.v2.b32 [%0], {%1, %2};" :: "r"(a), "r"(v0), "r"(v1) : "memory");
}
__device__ __forceinline__ void ldsm4t(uint32_t r[4], uint32_t a) {
    asm volatile("ldmatrix.sync.aligned.m8n8.x4.trans.shared.b16 {%0,%1,%2,%3}, [%4];"
                 : "=r"(r[0]), "=r"(r[1]), "=r"(r[2]), "=r"(r[3]) : "r"(a));
}
__device__ __forceinline__ void ldsm4(uint32_t r[4], uint32_t a) {
    asm volatile("ldmatrix.sync.aligned.m8n8.x4.shared.b16 {%0,%1,%2,%3}, [%4];"
                 : "=r"(r[0]), "=r"(r[1]), "=r"(r[2]), "=r"(r[3]) : "r"(a));
}
__device__ __forceinline__ void mma16816(float c[4], const uint32_t a[4], const uint32_t b[2]) {
    asm volatile(
        "mma.sync.aligned.m16n8k16.row.col.f32.bf16.bf16.f32 "
        "{%0,%1,%2,%3}, {%4,%5,%6,%7}, {%8,%9}, {%0,%1,%2,%3};"
        : "+f"(c[0]), "+f"(c[1]), "+f"(c[2]), "+f"(c[3])
        : "r"(a[0]), "r"(a[1]), "r"(a[2]), "r"(a[3]), "r"(b[0]), "r"(b[1]));
}
__device__ __forceinline__ uint32_t pack2h(float x, float y) {
    __half2 h = __floats2half2_rn(x, y);
    return *reinterpret_cast<uint32_t*>(&h);
}
// rounding bf16 split (proven): x ~= hi + lo, residual ~2^-17
__device__ __forceinline__ void split2(float x, float y, uint32_t& hi, uint32_t& lo) {
    __nv_bfloat162 h = __floats2bfloat162_rn(x, y);
    float2 hf = __bfloat1622float2(h);
    __nv_bfloat162 l = __floats2bfloat162_rn(x - hf.x, y - hf.y);
    hi = *reinterpret_cast<uint32_t*>(&h);
    lo = *reinterpret_cast<uint32_t*>(&l);
}

__global__ __launch_bounds__(128, 4)
void attn_kernel(const float* __restrict__ q, const float* __restrict__ k,
                 const float* __restrict__ v)
{
    extern __shared__ char smem[];
    const uint32_t sb = smem_u32(smem);
    const int tid = threadIdx.x, wp = tid >> 5, lane = tid & 31;
    const int g = blockIdx.x;
    const int b = g / NPP, rr = g - b * NPP;
    const int h0 = (rr / NWIN) * 4, w0 = (rr % NWIN) * 4;
    const size_t pbase = (size_t)b * CC * HW + (size_t)h0 * WW + w0;

    const int r8 = lane & 7, mi4 = lane >> 3;
    const int dmA = (mi4 & 1) << 3, dkA = (mi4 & 2) << 2;
    const uint32_t aXor = ((uint32_t)(32 * wp + 2 * dmA)) ^ ((uint32_t)r8 << 4);
    const int rowB = ((lane >> 3) & 1) * 8 + r8;
    const int ntSel = lane >> 4;
    const uint32_t rXor = (uint32_t)r8 << 4;

    float s[8][4];
#pragma unroll
    for (int i = 0; i < 8; ++i)
#pragma unroll
        for (int j = 0; j < 4; ++j) s[i][j] = 0.f;

    // ================= phase 1: S = Q K^T, two 64-channel chunks =================
    for (int ck = 0; ck < 2; ++ck) {
#pragma unroll
        for (int it = 0; it < 8; ++it) {
            int idx = tid + (it << 7);
            int cL = idx >> 4, t0 = (idx & 15) << 2;
            int c = ck * 64 + cL;
            size_t gp = pbase + (size_t)c * HW + (size_t)(t0 >> 3) * WW + (t0 & 7);
            float4 qv = *(const float4*)(q + gp);
            float4 kv = *(const float4*)(k + gp);
            uint32_t qh0, ql0, qh1, ql1, kh0, kl0, kh1, kl1;
            split2(qv.x * SCALE, qv.y * SCALE, qh0, ql0);
            split2(qv.z * SCALE, qv.w * SCALE, qh1, ql1);
            split2(kv.x, kv.y, kh0, kl0);
            split2(kv.z, kv.w, kh1, kl1);
            uint32_t off = sw128((uint32_t)(cL * 128 + t0 * 2));
            sts64(sb + QHc + off, qh0, qh1);
            sts64(sb + QLc + off, ql0, ql1);
            sts64(sb + KHc + off, kh0, kh1);
            sts64(sb + KLc + off, kl0, kl1);
        }
        __syncthreads();
#pragma unroll
        for (int kt = 0; kt < 4; ++kt) {
            uint32_t ah[4], al[4];
            uint32_t aA = sb + QHc + (uint32_t)((kt * 16 + dkA + r8) * 128) + aXor;
            ldsm4t(ah, aA);
            ldsm4t(al, aA + (QLc - QHc));
            uint32_t bRowA = sb + KHc + (uint32_t)((kt * 16 + rowB) * 128);
#pragma unroll
            for (int ntp = 0; ntp < 4; ++ntp) {
                uint32_t bh4[4], bl4[4];
                uint32_t baddr = bRowA + ((((uint32_t)(ntp * 2 + ntSel)) << 4) ^ rXor);
                ldsm4t(bh4, baddr);
                ldsm4t(bl4, baddr + (KLc - KHc));
                mma16816(s[2 * ntp], ah, bh4);
                mma16816(s[2 * ntp], ah, bl4);
                mma16816(s[2 * ntp], al, bh4);
                mma16816(s[2 * ntp + 1], ah, bh4 + 2);
                mma16816(s[2 * ntp + 1], ah, bl4 + 2);
                mma16816(s[2 * ntp + 1], al, bh4 + 2);
            }
        }
        __syncthreads();
    }

    // ---- load V [c][s] hi/lo (aliases phase-1 buffers) ----
#pragma unroll
    for (int it = 0; it < 16; ++it) {
        int idx = tid + (it << 7);
        int c = idx >> 4, t0 = (idx & 15) << 2;
        size_t gp = pbase + (size_t)c * HW + (size_t)(t0 >> 3) * WW + (t0 & 7);
        float4 vv = *(const float4*)(v + gp);
        uint32_t vh0, vl0, vh1, vl1;
        split2(vv.x, vv.y, vh0, vl0);
        split2(vv.z, vv.w, vh1, vl1);
        uint32_t off = sw128((uint32_t)(c * 128 + t0 * 2));
        sts64(sb + VHo + off, vh0, vh1);
        sts64(sb + VLo + off, vl0, vl1);
    }

    // ---- softmax in registers (row lives in 4 lanes) ----
    float mx0 = -1e30f, mx1 = -1e30f;
#pragma unroll
    for (int nt = 0; nt < 8; ++nt) {
        mx0 = fmaxf(mx0, fmaxf(s[nt][0], s[nt][1]));
        mx1 = fmaxf(mx1, fmaxf(s[nt][2], s[nt][3]));
    }
    mx0 = fmaxf(mx0, __shfl_xor_sync(~0u, mx0, 1));
    mx0 = fmaxf(mx0, __shfl_xor_sync(~0u, mx0, 2));
    mx1 = fmaxf(mx1, __shfl_xor_sync(~0u, mx1, 1));
    mx1 = fmaxf(mx1, __shfl_xor_sync(~0u, mx1, 2));
    float sm0 = 0.f, sm1 = 0.f;
#pragma unroll
    for (int nt = 0; nt < 8; ++nt) {
        s[nt][0] = __expf(s[nt][0] - mx0);
        s[nt][1] = __expf(s[nt][1] - mx0);
        s[nt][2] = __expf(s[nt][2] - mx1);
        s[nt][3] = __expf(s[nt][3] - mx1);
        sm0 += s[nt][0] + s[nt][1];
        sm1 += s[nt][2] + s[nt][3];
    }
    sm0 += __shfl_xor_sync(~0u, sm0, 1);
    sm0 += __shfl_xor_sync(~0u, sm0, 2);
    sm1 += __shfl_xor_sync(~0u, sm1, 1);
    sm1 += __shfl_xor_sync(~0u, sm1, 2);
    const float inv0 = 1.f / sm0, inv1 = 1.f / sm1;
    __syncthreads();   // V visible

    // ================= phase 2: Z = P V, two 64-channel halves =================
    uint32_t* tbu = reinterpret_cast<uint32_t*>(smem + TBo);   // packed half2 [t][cq]
    __half* zg = g_zbuf + (size_t)g * 8192;
    const int trow = 16 * wp + (lane >> 2);

    for (int hv = 0; hv < 2; ++hv) {
        float z[8][4];
#pragma unroll
        for (int i = 0; i < 8; ++i)
#pragma unroll
            for (int j = 0; j < 4; ++j) z[i][j] = 0.f;

#pragma unroll
        for (int kt = 0; kt < 4; ++kt) {
            uint32_t ph[4], pl[4];
            split2(s[2 * kt][0] * inv0, s[2 * kt][1] * inv0, ph[0], pl[0]);
            split2(s[2 * kt][2] * inv1, s[2 * kt][3] * inv1, ph[1], pl[1]);
            split2(s[2 * kt + 1][0] * inv0, s[2 * kt + 1][1] * inv0, ph[2], pl[2]);
            split2(s[2 * kt + 1][2] * inv1, s[2 * kt + 1][3] * inv1, ph[3], pl[3]);
            uint32_t vcol = ((uint32_t)((kt << 5) + (((lane >> 3) & 1) << 4))) ^ rXor;
#pragma unroll
            for (int ntp = 0; ntp < 4; ++ntp) {
                int row = hv * 64 + ntp * 16 + ntSel * 8 + r8;
                uint32_t addr = sb + VHo + (uint32_t)(row * 128) + vcol;
                uint32_t bh4[4], bl4[4];
                ldsm4(bh4, addr);
                ldsm4(bl4, addr + (VLo - VHo));
                mma16816(z[2 * ntp], ph, bh4);
                mma16816(z[2 * ntp], ph, bl4);
                mma16816(z[2 * ntp], pl, bh4);
                mma16816(z[2 * ntp + 1], ph, bh4 + 2);
                mma16816(z[2 * ntp + 1], ph, bl4 + 2);
                mma16816(z[2 * ntp + 1], pl, bh4 + 2);
            }
        }
        // pack + write TBu [t][cq]  (c pair -> one u32)
#pragma unroll
        for (int nt = 0; nt < 8; ++nt) {
            int cq = 4 * nt + (lane & 3);
            tbu[trow * TBU_S + cq]       = pack2h(z[nt][0], z[nt][1]);
            tbu[(trow + 8) * TBU_S + cq] = pack2h(z[nt][2], z[nt][3]);
        }
        __syncthreads();
        // store zbuf [t][c]: fully coalesced uint2 (stride 34 -> 8B-aligned)
#pragma unroll
        for (int it = 0; it < 8; ++it) {
            int idx = tid + (it << 7);
            int t = idx >> 4, cqp = idx & 15;
            uint2 u = *reinterpret_cast<const uint2*>(tbu + t * TBU_S + 2 * cqp);
            __stcs(reinterpret_cast<uint2*>(zg + t * 128 + hv * 64 + 4 * cqp), u);
        }
        __syncthreads();
    }
}

// ---- merge v4: half2 lanes + strength-reduced pointer walk ----
__global__ __launch_bounds__(256)
void merge_kernel(float* __restrict__ out)
{
    __shared__ float acc[128 * 65];               // [w][c(64)], pad 65
    const int h = blockIdx.x & 127;
    const int b = (blockIdx.x >> 7) & 7;
    const int cch = blockIdx.x >> 10;             // 0..1 -> 64 channels
    const int tid = threadIdx.x, wp = tid >> 5, lane = tid & 31;
    const int phmin = max(0, (h - 4) >> 2), phmax = min(h >> 2, 30);
    const __half2* zb2 = reinterpret_cast<const __half2*>(g_zbuf);
    // per-pw pointer step: +1 patch (4096 half2) - 4 t (256 half2)
    constexpr int PW_STEP = 4096 - 256;

#pragma unroll 4
    for (int wi = 0; wi < 16; ++wi) {
        int w = wp * 16 + wi;                     // warp owns w exclusively
        int pwmin = max(0, (w - 4) >> 2);
        int npw = min(w >> 2, 30) - pwmin + 1;
        float ax = 0.f, ay = 0.f;
        for (int ph = phmin; ph <= phmax; ++ph) {
            int dh = h - 4 * ph;
            const __half2* p = zb2
                + ((size_t)(b * NPP + ph * NWIN + pwmin) * 64 + dh * 8 + (w - 4 * pwmin)) * 64
                + cch * 32 + lane;
            for (int i = 0; i < npw; ++i) {
                float2 f = __half22float2(__ldcs(p));
                ax += f.x; ay += f.y;
                p += PW_STEP;
            }
        }
        acc[w * 65 + 2 * lane]     = ax;
        acc[w * 65 + 2 * lane + 1] = ay;
    }
    __syncthreads();

    // coalesced store: lane ~ w; 32 channels per thread-half
    const int w = tid & 127, cb = (tid >> 7) * 32;
    float* op = out + ((size_t)(b * 128 + cch * 64 + cb) * 128 + h) * 128 + w;
#pragma unroll 8
    for (int ci = 0; ci < 32; ++ci)
        op[(size_t)ci * HW] = acc[w * 65 + cb + ci];
}

extern "C" void kernel_launch(void* const* d_in, const int* in_sizes, int n_in,
                              void* d_out, int out_size)
{
    const float* q = (const float*)d_in[0];
    const float* k = (const float*)d_in[1];
    const float* v = (const float*)d_in[2];
    float* out = (float*)d_out;

    cudaFuncSetAttribute(attn_kernel,
                         cudaFuncAttributeMaxDynamicSharedMemorySize, SMEM_TOTAL);
    attn_kernel<<<NPATCH, 128, SMEM_TOTAL>>>(q, k, v);
    merge_kernel<<<8 * 128 * 2, 256>>>(out);
}

// round 14
// speedup vs baseline: 1.8962x; 1.2200x over previous
#include <cuda_runtime.h>
#include <cuda_bf16.h>
#include <cuda_fp16.h>
#include <cstdint>

constexpr int CC = 128, HH = 128, WW = 128, HW = HH * WW;
constexpr int NWIN = 31, NPP = NWIN * NWIN, NPATCH = 8 * NPP;   // 7688
constexpr float SCALE = 0.08838834764831845f;                    // 128^-0.5

constexpr int QHc = 0, QLc = 8192, KHc = 16384, KLc = 24576;
constexpr int VHo = 0, VLo = 16384, TBo = 32768;
constexpr int TBU_S = 34;
constexpr int SMEM_TOTAL = TBo + 64 * TBU_S * 4;                 // 41472

__device__ __half g_zbuf[(size_t)NPATCH * 64 * 128];             // [patch][t][c], fp16
__device__ __half g_zpad[128];                                   // zeros for edge contributors

__device__ __forceinline__ uint32_t smem_u32(const void* p) {
    uint32_t a;
    asm("{ .reg .u64 t; cvta.to.shared.u64 t, %1; cvt.u32.u64 %0, t; }" : "=r"(a) : "l"(p));
    return a;
}
__device__ __forceinline__ uint32_t sw128(uint32_t off) { return off ^ ((off >> 3) & 0x70); }
__device__ __forceinline__ void sts64(uint32_t a, uint32_t v0, uint32_t v1) {
    asm volatile("st.shared.v2.b32 [%0], {%1, %2};" :: "r"(a), "r"(v0), "r"(v1) : "memory");
}
__device__ __forceinline__ void ldsm4t(uint32_t r[4], uint32_t a) {
    asm volatile("ldmatrix.sync.aligned.m8n8.x4.trans.shared.b16 {%0,%1,%2,%3}, [%4];"
                 : "=r"(r[0]), "=r"(r[1]), "=r"(r[2]), "=r"(r[3]) : "r"(a));
}
__device__ __forceinline__ void ldsm4(uint32_t r[4], uint32_t a) {
    asm volatile("ldmatrix.sync.aligned.m8n8.x4.shared.b16 {%0,%1,%2,%3}, [%4];"
                 : "=r"(r[0]), "=r"(r[1]), "=r"(r[2]), "=r"(r[3]) : "r"(a));
}
__device__ __forceinline__ void mma16816(float c[4], const uint32_t a[4], const uint32_t b[2]) {
    asm volatile(
        "mma.sync.aligned.m16n8k16.row.col.f32.bf16.bf16.f32 "
        "{%0,%1,%2,%3}, {%4,%5,%6,%7}, {%8,%9}, {%0,%1,%2,%3};"
        : "+f"(c[0]), "+f"(c[1]), "+f"(c[2]), "+f"(c[3])
        : "r"(a[0]), "r"(a[1]), "r"(a[2]), "r"(a[3]), "r"(b[0]), "r"(b[1]));
}
__device__ __forceinline__ uint32_t pack2h(float x, float y) {
    __half2 h = __floats2half2_rn(x, y);
    return *reinterpret_cast<uint32_t*>(&h);
}
__device__ __forceinline__ void split2(float x, float y, uint32_t& hi, uint32_t& lo) {
    __nv_bfloat162 h = __floats2bfloat162_rn(x, y);
    float2 hf = __bfloat1622float2(h);
    __nv_bfloat162 l = __floats2bfloat162_rn(x - hf.x, y - hf.y);
    hi = *reinterpret_cast<uint32_t*>(&h);
    lo = *reinterpret_cast<uint32_t*>(&l);
}

__global__ __launch_bounds__(128, 4)
void attn_kernel(const float* __restrict__ q, const float* __restrict__ k,
                 const float* __restrict__ v)
{
    extern __shared__ char smem[];
    const uint32_t sb = smem_u32(smem);
    const int tid = threadIdx.x, wp = tid >> 5, lane = tid & 31;
    const int g = blockIdx.x;
    const int b = g / NPP, rr = g - b * NPP;
    const int h0 = (rr / NWIN) * 4, w0 = (rr % NWIN) * 4;
    const size_t pbase = (size_t)b * CC * HW + (size_t)h0 * WW + w0;

    const int r8 = lane & 7, mi4 = lane >> 3;
    const int dmA = (mi4 & 1) << 3, dkA = (mi4 & 2) << 2;
    const uint32_t aXor = ((uint32_t)(32 * wp + 2 * dmA)) ^ ((uint32_t)r8 << 4);
    const int rowB = ((lane >> 3) & 1) * 8 + r8;
    const int ntSel = lane >> 4;
    const uint32_t rXor = (uint32_t)r8 << 4;

    float s[8][4];
#pragma unroll
    for (int i = 0; i < 8; ++i)
#pragma unroll
        for (int j = 0; j < 4; ++j) s[i][j] = 0.f;

    for (int ck = 0; ck < 2; ++ck) {
#pragma unroll
        for (int it = 0; it < 8; ++it) {
            int idx = tid + (it << 7);
            int cL = idx >> 4, t0 = (idx & 15) << 2;
            int c = ck * 64 + cL;
            size_t gp = pbase + (size_t)c * HW + (size_t)(t0 >> 3) * WW + (t0 & 7);
            float4 qv = *(const float4*)(q + gp);
            float4 kv = *(const float4*)(k + gp);
            uint32_t qh0, ql0, qh1, ql1, kh0, kl0, kh1, kl1;
            split2(qv.x * SCALE, qv.y * SCALE, qh0, ql0);
            split2(qv.z * SCALE, qv.w * SCALE, qh1, ql1);
            split2(kv.x, kv.y, kh0, kl0);
            split2(kv.z, kv.w, kh1, kl1);
            uint32_t off = sw128((uint32_t)(cL * 128 + t0 * 2));
            sts64(sb + QHc + off, qh0, qh1);
            sts64(sb + QLc + off, ql0, ql1);
            sts64(sb + KHc + off, kh0, kh1);
            sts64(sb + KLc + off, kl0, kl1);
        }
        __syncthreads();
#pragma unroll
        for (int kt = 0; kt < 4; ++kt) {
            uint32_t ah[4], al[4];
            uint32_t aA = sb + QHc + (uint32_t)((kt * 16 + dkA + r8) * 128) + aXor;
            ldsm4t(ah, aA);
            ldsm4t(al, aA + (QLc - QHc));
            uint32_t bRowA = sb + KHc + (uint32_t)((kt * 16 + rowB) * 128);
#pragma unroll
            for (int ntp = 0; ntp < 4; ++ntp) {
                uint32_t bh4[4], bl4[4];
                uint32_t baddr = bRowA + ((((uint32_t)(ntp * 2 + ntSel)) << 4) ^ rXor);
                ldsm4t(bh4, baddr);
                ldsm4t(bl4, baddr + (KLc - KHc));
                mma16816(s[2 * ntp], ah, bh4);
                mma16816(s[2 * ntp], ah, bl4);
                mma16816(s[2 * ntp], al, bh4);
                mma16816(s[2 * ntp + 1], ah, bh4 + 2);
                mma16816(s[2 * ntp + 1], ah, bl4 + 2);
                mma16816(s[2 * ntp + 1], al, bh4 + 2);
            }
        }
        __syncthreads();
    }

#pragma unroll
    for (int it = 0; it < 16; ++it) {
        int idx = tid + (it << 7);
        int c = idx >> 4, t0 = (idx & 15) << 2;
        size_t gp = pbase + (size_t)c * HW + (size_t)(t0 >> 3) * WW + (t0 & 7);
        float4 vv = *(const float4*)(v + gp);
        uint32_t vh0, vl0, vh1, vl1;
        split2(vv.x, vv.y, vh0, vl0);
        split2(vv.z, vv.w, vh1, vl1);
        uint32_t off = sw128((uint32_t)(c * 128 + t0 * 2));
        sts64(sb + VHo + off, vh0, vh1);
        sts64(sb + VLo + off, vl0, vl1);
    }

    float mx0 = -1e30f, mx1 = -1e30f;
#pragma unroll
    for (int nt = 0; nt < 8; ++nt) {
        mx0 = fmaxf(mx0, fmaxf(s[nt][0], s[nt][1]));
        mx1 = fmaxf(mx1, fmaxf(s[nt][2], s[nt][3]));
    }
    mx0 = fmaxf(mx0, __shfl_xor_sync(~0u, mx0, 1));
    mx0 = fmaxf(mx0, __shfl_xor_sync(~0u, mx0, 2));
    mx1 = fmaxf(mx1, __shfl_xor_sync(~0u, mx1, 1));
    mx1 = fmaxf(mx1, __shfl_xor_sync(~0u, mx1, 2));
    float sm0 = 0.f, sm1 = 0.f;
#pragma unroll
    for (int nt = 0; nt < 8; ++nt) {
        s[nt][0] = __expf(s[nt][0] - mx0);
        s[nt][1] = __expf(s[nt][1] - mx0);
        s[nt][2] = __expf(s[nt][2] - mx1);
        s[nt][3] = __expf(s[nt][3] - mx1);
        sm0 += s[nt][0] + s[nt][1];
        sm1 += s[nt][2] + s[nt][3];
    }
    sm0 += __shfl_xor_sync(~0u, sm0, 1);
    sm0 += __shfl_xor_sync(~0u, sm0, 2);
    sm1 += __shfl_xor_sync(~0u, sm1, 1);
    sm1 += __shfl_xor_sync(~0u, sm1, 2);
    const float inv0 = 1.f / sm0, inv1 = 1.f / sm1;
    __syncthreads();

    uint32_t* tbu = reinterpret_cast<uint32_t*>(smem + TBo);
    __half* zg = g_zbuf + (size_t)g * 8192;
    const int trow = 16 * wp + (lane >> 2);

    for (int hv = 0; hv < 2; ++hv) {
        float z[8][4];
#pragma unroll
        for (int i = 0; i < 8; ++i)
#pragma unroll
            for (int j = 0; j < 4; ++j) z[i][j] = 0.f;

#pragma unroll
        for (int kt = 0; kt < 4; ++kt) {
            uint32_t ph[4], pl[4];
            split2(s[2 * kt][0] * inv0, s[2 * kt][1] * inv0, ph[0], pl[0]);
            split2(s[2 * kt][2] * inv1, s[2 * kt][3] * inv1, ph[1], pl[1]);
            split2(s[2 * kt + 1][0] * inv0, s[2 * kt + 1][1] * inv0, ph[2], pl[2]);
            split2(s[2 * kt + 1][2] * inv1, s[2 * kt + 1][3] * inv1, ph[3], pl[3]);
            uint32_t vcol = ((uint32_t)((kt << 5) + (((lane >> 3) & 1) << 4))) ^ rXor;
#pragma unroll
            for (int ntp = 0; ntp < 4; ++ntp) {
                int row = hv * 64 + ntp * 16 + ntSel * 8 + r8;
                uint32_t addr = sb + VHo + (uint32_t)(row * 128) + vcol;
                uint32_t bh4[4], bl4[4];
                ldsm4(bh4, addr);
                ldsm4(bl4, addr + (VLo - VHo));
                mma16816(z[2 * ntp], ph, bh4);
                mma16816(z[2 * ntp], ph, bl4);
                mma16816(z[2 * ntp], pl, bh4);
                mma16816(z[2 * ntp + 1], ph, bh4 + 2);
                mma16816(z[2 * ntp + 1], ph, bl4 + 2);
                mma16816(z[2 * ntp + 1], pl, bh4 + 2);
            }
        }
#pragma unroll
        for (int nt = 0; nt < 8; ++nt) {
            int cq = 4 * nt + (lane & 3);
            tbu[trow * TBU_S + cq]       = pack2h(z[nt][0], z[nt][1]);
            tbu[(trow + 8) * TBU_S + cq] = pack2h(z[nt][2], z[nt][3]);
        }
        __syncthreads();
#pragma unroll
        for (int it = 0; it < 8; ++it) {
            int idx = tid + (it << 7);
            int t = idx >> 4, cqp = idx & 15;
            uint2 u = *reinterpret_cast<const uint2*>(tbu + t * TBU_S + 2 * cqp);
            __stcs(reinterpret_cast<uint2*>(zg + t * 128 + hv * 64 + 4 * cqp), u);
        }
        __syncthreads();
    }
}

// ---- merge v5: static 4-contributor form, zero-pad edges, max MLP ----
__global__ __launch_bounds__(256)
void merge_kernel(float* __restrict__ out)
{
    __shared__ float acc[128 * 65];               // [w][c(64)], pad 65
    const int h = blockIdx.x & 127;
    const int b = (blockIdx.x >> 7) & 7;
    const int cch = blockIdx.x >> 10;             // 0..1 -> 64 channels
    const int tid = threadIdx.x, wp = tid >> 5, lane = tid & 31;
    const __half2* zb2 = reinterpret_cast<const __half2*>(g_zbuf);
    const __half2* zp = reinterpret_cast<const __half2*>(g_zpad) + lane;

    // ph candidates: phb = h>>2 (dh = h&3), pha = phb-1 (dh = (h&3)+4)
    const int phb = h >> 2, pha = phb - 1;
    const bool phaV = (pha >= 0), phbV = (phb <= 30);
    // B(ph) in half2 units: (b*NPP + ph*31)*4096 + dh*8*64 + cch*32 + lane
    const size_t BA = phaV ? ((size_t)(b * NPP + pha * NWIN) * 4096
                              + (size_t)((h & 3) + 4) * 512 + cch * 32 + lane) : 0;
    const size_t BB = phbV ? ((size_t)(b * NPP + phb * NWIN) * 4096
                              + (size_t)(h & 3) * 512 + cch * 32 + lane) : 0;

#pragma unroll
    for (int wi = 0; wi < 16; ++wi) {
        const int w = wp * 16 + wi;               // warp owns w exclusively
        const int pwb = w >> 2, pwa = pwb - 1;
        const bool pwaV = (pwa >= 0), pwbV = (pwb <= 30);
        const size_t woff = (size_t)w * 64;
        const size_t offA = woff + (size_t)pwa * 3840;   // addr = B + w*64 + pw*3840
        const size_t offB = woff + (size_t)pwb * 3840;

        const __half2* p0 = (phaV && pwaV) ? zb2 + BA + offA : zp;
        const __half2* p1 = (phaV && pwbV) ? zb2 + BA + offB : zp;
        const __half2* p2 = (phbV && pwaV) ? zb2 + BB + offA : zp;
        const __half2* p3 = (phbV && pwbV) ? zb2 + BB + offB : zp;

        __half2 v0 = __ldcs(p0), v1 = __ldcs(p1), v2 = __ldcs(p2), v3 = __ldcs(p3);
        float2 f0 = __half22float2(v0), f1 = __half22float2(v1);
        float2 f2 = __half22float2(v2), f3 = __half22float2(v3);
        acc[w * 65 + 2 * lane]     = (f0.x + f1.x) + (f2.x + f3.x);
        acc[w * 65 + 2 * lane + 1] = (f0.y + f1.y) + (f2.y + f3.y);
    }
    __syncthreads();

    const int w = tid & 127, cb = (tid >> 7) * 32;
    float* op = out + ((size_t)(b * 128 + cch * 64 + cb) * 128 + h) * 128 + w;
#pragma unroll 8
    for (int ci = 0; ci < 32; ++ci)
        op[(size_t)ci * HW] = acc[w * 65 + cb + ci];
}

extern "C" void kernel_launch(void* const* d_in, const int* in_sizes, int n_in,
                              void* d_out, int out_size)
{
    const float* q = (const float*)d_in[0];
    const float* k = (const float*)d_in[1];
    const float* v = (const float*)d_in[2];
    float* out = (float*)d_out;

    cudaFuncSetAttribute(attn_kernel,
                         cudaFuncAttributeMaxDynamicSharedMemorySize, SMEM_TOTAL);
    attn_kernel<<<NPATCH, 128, SMEM_TOTAL>>>(q, k, v);
    merge_kernel<<<8 * 128 * 2, 256>>>(out);
}